// round 17
// baseline (speedup 1.0000x reference)
#include <cuda_runtime.h>
#include <cuda_fp16.h>
#include <cstdint>

// ---------------------------------------------------------------------------
// Problem constants
// ---------------------------------------------------------------------------
#define M_ 4096
#define N_ 12288
#define K_ 4096
#define NW_ (N_ / 8)          // packed int32 words per k-row = 1536

// ---------------------------------------------------------------------------
// GEMM tiling: CTA 128x256x64, 8 warps (2x4), warp tile 64x64, mma.m16n8k16
// Fused in-GEMM dequant: B loaded as int4 words, unpacked to fp16 in regs,
// STS into smem. A via cp.async. 3 stages, single barrier per k-tile.
// ---------------------------------------------------------------------------
#define BM 128
#define BN 256
#define BK 64
#define STAGES 3
#define KTILES (K_ / BK)        // 64
#define THREADS 256

// SMEM layout per stage (fp16):
//  A: [128 rows][64 halves + 8 pad]  pitch 144B (9x16B chunks, coprime 8)
//  B: [64 rows][256 halves + 8 pad]  pitch 528B (33x16B chunks, coprime 8)
#define A_PITCH 144
#define B_PITCH 528
#define A_STAGE (BM * A_PITCH)              // 18432
#define B_STAGE (BK * B_PITCH)              // 33792
#define STAGE_BYTES (A_STAGE + B_STAGE)     // 52224
#define SMEM_TOTAL (STAGES * STAGE_BYTES)   // 156672

// Scratch: fp16 activations only (weights dequantized inside GEMM)
__device__ __half g_X[(size_t)M_ * K_];

// ---------------------------------------------------------------------------
// Helpers
// ---------------------------------------------------------------------------
__device__ __forceinline__ unsigned smem_u32(const void* p) {
    unsigned a;
    asm("{ .reg .u64 t; cvta.to.shared.u64 t, %1; cvt.u32.u64 %0, t; }" : "=r"(a) : "l"(p));
    return a;
}
__device__ __forceinline__ void cp_async16(unsigned dst, const void* src) {
    asm volatile("cp.async.cg.shared.global [%0], [%1], 16;\n" :: "r"(dst), "l"(src));
}
__device__ __forceinline__ void ldsm4(unsigned r[4], unsigned addr) {
    asm volatile("ldmatrix.sync.aligned.m8n8.x4.shared.b16 {%0,%1,%2,%3}, [%4];"
                 : "=r"(r[0]), "=r"(r[1]), "=r"(r[2]), "=r"(r[3]) : "r"(addr));
}
__device__ __forceinline__ void ldsm4t(unsigned r[4], unsigned addr) {
    asm volatile("ldmatrix.sync.aligned.m8n8.x4.trans.shared.b16 {%0,%1,%2,%3}, [%4];"
                 : "=r"(r[0]), "=r"(r[1]), "=r"(r[2]), "=r"(r[3]) : "r"(addr));
}
__device__ __forceinline__ void mma16816(float c[4], const unsigned a[4], const unsigned b[2]) {
    asm volatile(
        "mma.sync.aligned.m16n8k16.row.col.f32.f16.f16.f32 "
        "{%0,%1,%2,%3}, {%4,%5,%6,%7}, {%8,%9}, {%0,%1,%2,%3};\n"
        : "+f"(c[0]), "+f"(c[1]), "+f"(c[2]), "+f"(c[3])
        : "r"(a[0]), "r"(a[1]), "r"(a[2]), "r"(a[3]), "r"(b[0]), "r"(b[1]));
}
__device__ __forceinline__ unsigned pack2(float lo, float hi) {
    __half2 h = __halves2half2(__float2half_rn(lo), __float2half_rn(hi));
    return *reinterpret_cast<unsigned*>(&h);
}

// ---------------------------------------------------------------------------
// Kernel 1: x -> fp16 g_X
// ---------------------------------------------------------------------------
__global__ void round_x_kernel(const float* __restrict__ x) {
    size_t i = ((size_t)blockIdx.x * blockDim.x + threadIdx.x) * 8;
    float4 v0 = *reinterpret_cast<const float4*>(x + i);
    float4 v1 = *reinterpret_cast<const float4*>(x + i + 4);
    uint4 o;
    o.x = pack2(v0.x, v0.y);
    o.y = pack2(v0.z, v0.w);
    o.z = pack2(v1.x, v1.y);
    o.w = pack2(v1.z, v1.w);
    *reinterpret_cast<uint4*>(g_X + i) = o;
}

// ---------------------------------------------------------------------------
// Kernel 2: fp16 GEMM with fused int4 dequant for B.
// out = x @ dequant(qw) + bias,  fp32 accumulate.
// ---------------------------------------------------------------------------
__global__ __launch_bounds__(THREADS, 1)
void gemm_f16_kernel(const int* __restrict__ qw,
                     const int* __restrict__ qz,
                     const float* __restrict__ sc,
                     const float* __restrict__ bias,
                     float* __restrict__ out) {
    extern __shared__ char dsmem[];
    const unsigned smem_base = smem_u32(dsmem);

    const int tid  = threadIdx.x;
    const int lane = tid & 31;
    const int warp = tid >> 5;
    const int wm = warp >> 2;          // 0..1  (64-row slab)
    const int wn = warp & 3;           // 0..3  (64-col slab)

    // L2-friendly CTA swizzle: groups of 8 M-tiles share B panels
    const int PN = N_ / BN;            // 48
    const int GROUP = 8;
    int bid = blockIdx.x;
    int grp = bid / (GROUP * PN);
    int rem = bid % (GROUP * PN);
    int bm = grp * GROUP + (rem % GROUP);   // 0..31
    int bn = rem / GROUP;                   // 0..47

    const __half* Ag = g_X + (size_t)(bm * BM) * K_;

    // ---- B dequant thread mapping: 256 thr = 32 word-cols x 8 row-groups
    const int wcol = tid & 31;              // packed word within panel
    const int rg   = tid >> 5;              // row-group: rows rg*8 .. rg*8+7
    const int wg   = bn * 32 + wcol;        // global packed-word index

    // B pipeline registers (1 tile ahead)
    int   qreg[8];
    int   zreg;
    float4 s0reg, s1reg;

    auto ldgB = [&](int kt) {
        const int g = kt >> 1;              // GS=128, BK=64
        const int* qp = qw + (size_t)(kt * BK + rg * 8) * NW_ + wg;
#pragma unroll
        for (int i = 0; i < 8; i++) qreg[i] = qp[(size_t)i * NW_];
        zreg = qz[(size_t)g * NW_ + wg];
        const float4* sp = reinterpret_cast<const float4*>(sc + (size_t)g * N_ + (size_t)wg * 8);
        s0reg = sp[0];
        s1reg = sp[1];
    };

    auto fillB = [&](int kt) {
        const unsigned sb = smem_base + (unsigned)((kt % STAGES) * STAGE_BYTES) + A_STAGE;
        float s[8] = {s0reg.x, s0reg.y, s0reg.z, s0reg.w,
                      s1reg.x, s1reg.y, s1reg.z, s1reg.w};
        int zn[8];
#pragma unroll
        for (int j = 0; j < 8; j++) zn[j] = (zreg >> (4 * j)) & 0xF;
#pragma unroll
        for (int i = 0; i < 8; i++) {
            int q = qreg[i];
            float o[8];
#pragma unroll
            for (int j = 0; j < 8; j++)
                o[j] = (float)(((q >> (4 * j)) & 0xF) - zn[j]) * s[j];
            uint4 pk;
            pk.x = pack2(o[0], o[1]);
            pk.y = pack2(o[2], o[3]);
            pk.z = pack2(o[4], o[5]);
            pk.w = pack2(o[6], o[7]);
            unsigned dst = sb + (unsigned)((rg * 8 + i) * B_PITCH + wcol * 16);
            asm volatile("st.shared.v4.b32 [%0], {%1,%2,%3,%4};"
                         :: "r"(dst), "r"(pk.x), "r"(pk.y), "r"(pk.z), "r"(pk.w) : "memory");
        }
    };

    auto loadA = [&](int kt) {
        const unsigned sa = smem_base + (unsigned)((kt % STAGES) * STAGE_BYTES);
        // A: 128 rows x 8 chunks = 1024 chunks, 4 per thread
#pragma unroll
        for (int i = 0; i < 4; i++) {
            int ch = tid + i * 256;
            int row = ch >> 3, c = ch & 7;
            cp_async16(sa + (unsigned)(row * A_PITCH + c * 16),
                       Ag + (size_t)row * K_ + kt * BK + c * 8);
        }
    };

    float acc[4][8][4];
#pragma unroll
    for (int mi = 0; mi < 4; mi++)
#pragma unroll
        for (int ni = 0; ni < 8; ni++)
#pragma unroll
            for (int r = 0; r < 4; r++) acc[mi][ni][r] = 0.0f;

    // Per-lane ldmatrix address components
    const unsigned a_lds_row = (unsigned)((wm * 64 + (lane & 15)) * A_PITCH + (lane >> 4) * 16);
    const unsigned b_lds_col = (unsigned)((wn * 64 + (lane >> 4) * 8) * 2);
    const unsigned b_lds_row = (unsigned)((lane & 15) * B_PITCH);

    // ---- Prologue ----
    ldgB(0);
    loadA(0); asm volatile("cp.async.commit_group;\n");
    loadA(1); asm volatile("cp.async.commit_group;\n");
    fillB(0);           // stalls on ldgB(0) latency once
    ldgB(1);

    for (int kt = 0; kt < KTILES; kt++) {
        // 1) STS next B tile from regs (stage (kt+1)%3; its previous tile
        //    kt-2 was consumed before two intervening barriers)
        if (kt + 1 < KTILES) fillB(kt + 1);
        // 2) prefetch B regs for kt+2 (latency hidden by compute(kt))
        if (kt + 2 < KTILES) ldgB(kt + 2);
        // 3) retire A(kt): outstanding groups {A(kt), A(kt+1)}
        asm volatile("cp.async.wait_group 1;\n" ::: "memory");
        __syncthreads();
        // 4) A stage (kt+2)%3 == (kt-1)%3: compute(kt-1) done by all warps
        if (kt + 2 < KTILES) loadA(kt + 2);
        asm volatile("cp.async.commit_group;\n");   // empty commit keeps count exact

        const unsigned so = (unsigned)((kt % STAGES) * STAGE_BYTES);
        const unsigned sa = smem_base + so;
        const unsigned sb = sa + A_STAGE;

#pragma unroll
        for (int kk = 0; kk < 4; kk++) {            // four k16 sub-steps
            unsigned af[4][4];
            unsigned bf[8][2];
#pragma unroll
            for (int mi = 0; mi < 4; mi++)
                ldsm4(af[mi], sa + a_lds_row + (unsigned)(mi * 16 * A_PITCH)
                                 + (unsigned)(kk * 32));
#pragma unroll
            for (int nb = 0; nb < 4; nb++) {
                unsigned t[4];
                ldsm4t(t, sb + b_lds_row + (unsigned)(kk * 16 * B_PITCH)
                          + b_lds_col + (unsigned)(nb * 32));
                bf[2 * nb + 0][0] = t[0]; bf[2 * nb + 0][1] = t[1];
                bf[2 * nb + 1][0] = t[2]; bf[2 * nb + 1][1] = t[3];
            }
#pragma unroll
            for (int mi = 0; mi < 4; mi++)
#pragma unroll
                for (int ni = 0; ni < 8; ni++)
                    mma16816(acc[mi][ni], af[mi], bf[ni]);
        }
    }

    // Epilogue: bias add, fp32 stores
    const int row_base = bm * BM + wm * 64 + (lane >> 2);
    const int col_base = bn * BN + wn * 64 + (lane & 3) * 2;
#pragma unroll
    for (int mi = 0; mi < 4; mi++) {
        int row = row_base + mi * 16;
#pragma unroll
        for (int ni = 0; ni < 8; ni++) {
            int col = col_base + ni * 8;
            float2 bv = *reinterpret_cast<const float2*>(bias + col);
            float2 o0 = make_float2(acc[mi][ni][0] + bv.x, acc[mi][ni][1] + bv.y);
            float2 o1 = make_float2(acc[mi][ni][2] + bv.x, acc[mi][ni][3] + bv.y);
            *reinterpret_cast<float2*>(out + (size_t)row * N_ + col) = o0;
            *reinterpret_cast<float2*>(out + (size_t)(row + 8) * N_ + col) = o1;
        }
    }
}

// ---------------------------------------------------------------------------
extern "C" void kernel_launch(void* const* d_in, const int* in_sizes, int n_in,
                              void* d_out, int out_size) {
    const float* x    = (const float*)d_in[0];
    const int*   qw   = (const int*)d_in[1];
    const int*   qz   = (const int*)d_in[2];
    const float* sc   = (const float*)d_in[3];
    const float* bias = (const float*)d_in[4];
    float* out = (float*)d_out;

    // 1) x -> fp16
    round_x_kernel<<<(M_ * (size_t)K_) / 8 / 256, 256>>>(x);
    // 2) fused dequant + fp16 tensor-core GEMM + bias
    cudaFuncSetAttribute(gemm_f16_kernel,
                         cudaFuncAttributeMaxDynamicSharedMemorySize, SMEM_TOTAL);
    gemm_f16_kernel<<<(M_ / BM) * (N_ / BN), THREADS, SMEM_TOTAL>>>(qw, qz, sc, bias, out);
}